// round 4
// baseline (speedup 1.0000x reference)
#include <cuda_runtime.h>

#define NNODES  50000
#define HID     128
#define NEDGES  600000
#define OUTC    40
#define NLAYERS 3

// Persistent scratch (allocation-free rule: __device__ globals).
__device__ float g_h[(size_t)NNODES * HID];
__device__ float g_z[(size_t)NNODES * HID];

// ---------------- packed f32x2 helpers (sm_103a) ----------------
__device__ __forceinline__ unsigned long long pack2(float a, float b) {
    unsigned long long r;
    asm("mov.b64 %0, {%1,%2};" : "=l"(r) : "f"(a), "f"(b));
    return r;
}
__device__ __forceinline__ void unpack2(unsigned long long v, float& a, float& b) {
    asm("mov.b64 {%0,%1}, %2;" : "=f"(a), "=f"(b) : "l"(v));
}
__device__ __forceinline__ unsigned long long fma2(unsigned long long a,
                                                   unsigned long long b,
                                                   unsigned long long c) {
    unsigned long long d;
    asm("fma.rn.f32x2 %0, %1, %2, %3;" : "=l"(d) : "l"(a), "l"(b), "l"(c));
    return d;
}

// ---------------- scatter-add: z[dst,:] += h[src,:] ----------------
// One warp per edge; each lane owns 16 bytes (float4). h and z are L2-resident
// (25.6 MB each), so this is LTS-throughput bound. Vector red quarters the
// atomic op count vs scalar atomicAdd.
// edge_index arrives as INT32 (JAX x64-disabled demotes int64 -> int32).
__global__ __launch_bounds__(256) void scatter_kernel(
        const float* __restrict__ h, float* __restrict__ z,
        const int* __restrict__ ei) {
    int w = (blockIdx.x * blockDim.x + threadIdx.x) >> 5;
    if (w >= NEDGES) return;
    int lane = threadIdx.x & 31;
    int src = __ldg(&ei[w]);
    int dst = __ldg(&ei[NEDGES + w]);
    float4 v = *(const float4*)(h + (size_t)src * HID + lane * 4);
    float* p = z + (size_t)dst * HID + lane * 4;
    asm volatile("red.global.add.v4.f32 [%0], {%1,%2,%3,%4};"
                 :: "l"(p), "f"(v.x), "f"(v.y), "f"(v.z), "f"(v.w)
                 : "memory");
}

// ---------------- fused GIN MLP: h' = relu( relu(z@W1+b1)@W2 + b2 ) --------
// Tile: 64 rows x 128 cols, 256 threads, each thread 4 rows x 4 col-pairs
// (32 outputs) using packed fma.rn.f32x2.
//   zs2: z tile duplicated as {v,v} pairs, row-padded to 129 (conflict-free
//        broadcast loads).
//   Ws : weight matrix staged row-major; 16 tx lanes x LDS.64 read 128
//        contiguous bytes (conflict-free, broadcast across ty).
// Hidden activation stays in SMEM (zs2 reused); Ws reused for W2.
// Epilogue writes BOTH hout (next h) and zout (next z init) -> no per-layer
// device memcpy.
#define MLP_SMEM (64 * 129 * 8 + 128 * 128 * 4)

__global__ __launch_bounds__(256) void mlp_kernel(
        const float* __restrict__ zin,
        float* __restrict__ hout, float* __restrict__ zout,
        const float* __restrict__ W1, const float* __restrict__ b1,
        const float* __restrict__ W2, const float* __restrict__ b2) {
    extern __shared__ unsigned long long smem[];
    unsigned long long* zs2 = smem;                       // [64][129] f32x2
    float* Ws = (float*)(smem + 64 * 129);                // [128][128]
    __shared__ float bs[HID];

    const int tid = threadIdx.x;
    const int tx = tid & 15;       // col-pair group
    const int ty = tid >> 4;       // row group (4 rows)
    const int row0 = blockIdx.x * 64;
    const int rmax = NNODES - row0;

    // Stage z tile (duplicated pairs) + W1 + b1
    for (int i = tid; i < 64 * HID; i += 256) {
        int r = i >> 7, k = i & 127;
        float v = (r < rmax) ? zin[(size_t)(row0 + r) * HID + k] : 0.f;
        zs2[r * 129 + k] = pack2(v, v);
    }
    for (int i = tid; i < HID * HID / 4; i += 256)
        ((float4*)Ws)[i] = ((const float4*)W1)[i];
    if (tid < HID) bs[tid] = b1[tid];
    __syncthreads();

    unsigned long long acc[4][4];

    // ---- phase 1: hidden = relu(z @ W1 + b1) ----
    #pragma unroll
    for (int q = 0; q < 4; q++) {
        int c = 2 * tx + 32 * q;
        unsigned long long bq = pack2(bs[c], bs[c + 1]);
        #pragma unroll
        for (int i = 0; i < 4; i++) acc[i][q] = bq;
    }
    #pragma unroll 4
    for (int k = 0; k < HID; k++) {
        unsigned long long zp[4], wp[4];
        #pragma unroll
        for (int i = 0; i < 4; i++) zp[i] = zs2[(ty * 4 + i) * 129 + k];
        #pragma unroll
        for (int q = 0; q < 4; q++)
            wp[q] = *(const unsigned long long*)(Ws + k * HID + 2 * tx + 32 * q);
        #pragma unroll
        for (int i = 0; i < 4; i++)
            #pragma unroll
            for (int q = 0; q < 4; q++)
                acc[i][q] = fma2(zp[i], wp[q], acc[i][q]);
    }
    __syncthreads();   // everyone done reading zs2/Ws

    // hidden (relu, duplicated) -> zs2 ; stage W2 + b2
    #pragma unroll
    for (int i = 0; i < 4; i++) {
        int r = ty * 4 + i;
        #pragma unroll
        for (int q = 0; q < 4; q++) {
            float a, b; unpack2(acc[i][q], a, b);
            a = fmaxf(a, 0.f); b = fmaxf(b, 0.f);
            int c = 2 * tx + 32 * q;
            zs2[r * 129 + c]     = pack2(a, a);
            zs2[r * 129 + c + 1] = pack2(b, b);
        }
    }
    for (int i = tid; i < HID * HID / 4; i += 256)
        ((float4*)Ws)[i] = ((const float4*)W2)[i];
    if (tid < HID) bs[tid] = b2[tid];
    __syncthreads();

    // ---- phase 2: out = relu(hidden @ W2 + b2) ----
    #pragma unroll
    for (int q = 0; q < 4; q++) {
        int c = 2 * tx + 32 * q;
        unsigned long long bq = pack2(bs[c], bs[c + 1]);
        #pragma unroll
        for (int i = 0; i < 4; i++) acc[i][q] = bq;
    }
    #pragma unroll 4
    for (int k = 0; k < HID; k++) {
        unsigned long long zp[4], wp[4];
        #pragma unroll
        for (int i = 0; i < 4; i++) zp[i] = zs2[(ty * 4 + i) * 129 + k];
        #pragma unroll
        for (int q = 0; q < 4; q++)
            wp[q] = *(const unsigned long long*)(Ws + k * HID + 2 * tx + 32 * q);
        #pragma unroll
        for (int i = 0; i < 4; i++)
            #pragma unroll
            for (int q = 0; q < 4; q++)
                acc[i][q] = fma2(zp[i], wp[q], acc[i][q]);
    }

    // epilogue: relu -> hout AND zout (z init for next layer's scatter)
    #pragma unroll
    for (int i = 0; i < 4; i++) {
        int r = ty * 4 + i;
        if (r < rmax) {
            #pragma unroll
            for (int q = 0; q < 4; q++) {
                float a, b; unpack2(acc[i][q], a, b);
                a = fmaxf(a, 0.f); b = fmaxf(b, 0.f);
                size_t o = (size_t)(row0 + r) * HID + 2 * tx + 32 * q;
                hout[o] = a; hout[o + 1] = b;
                zout[o] = a; zout[o + 1] = b;
            }
        }
    }
}

// ---------------- classifier: out = h @ Wc + bc ----------------
// 32-row tile, 256 threads: thread (ty=row, tx -> 5 cols).
__global__ __launch_bounds__(256) void cls_kernel(
        const float* __restrict__ h, const float* __restrict__ Wc,
        const float* __restrict__ bc, float* __restrict__ out) {
    __shared__ float hs[32][129];
    __shared__ float Ws[HID * OUTC];
    __shared__ float bsc[OUTC];

    const int tid = threadIdx.x;
    const int row0 = blockIdx.x * 32;

    for (int i = tid; i < 32 * HID; i += 256) {
        int r = i >> 7, k = i & 127;
        hs[r][k] = (row0 + r < NNODES) ? h[(size_t)(row0 + r) * HID + k] : 0.f;
    }
    for (int i = tid; i < HID * OUTC; i += 256) Ws[i] = Wc[i];
    if (tid < OUTC) bsc[tid] = bc[tid];
    __syncthreads();

    const int ty = tid >> 3;   // row 0..31
    const int tx = tid & 7;    // col group: cols tx*5 .. tx*5+4

    float acc[5];
    #pragma unroll
    for (int c = 0; c < 5; c++) acc[c] = bsc[tx * 5 + c];
    #pragma unroll 4
    for (int k = 0; k < HID; k++) {
        float hv = hs[ty][k];
        #pragma unroll
        for (int c = 0; c < 5; c++)
            acc[c] = fmaf(hv, Ws[k * OUTC + tx * 5 + c], acc[c]);
    }
    int r = row0 + ty;
    if (r < NNODES) {
        #pragma unroll
        for (int c = 0; c < 5; c++) out[(size_t)r * OUTC + tx * 5 + c] = acc[c];
    }
}

// ---------------- launch ----------------
extern "C" void kernel_launch(void* const* d_in, const int* in_sizes, int n_in,
                              void* d_out, int out_size) {
    (void)in_sizes; (void)n_in; (void)out_size;
    const float* x  = (const float*)d_in[0];
    // d_in[1] = edge_attr (unused by the reference)
    const int*   ei = (const int*)d_in[2];       // int32 (JAX demotes int64)
    const float* W1 = (const float*)d_in[3];
    const float* b1 = (const float*)d_in[4];
    const float* W2 = (const float*)d_in[5];
    const float* b2 = (const float*)d_in[6];
    const float* Wc = (const float*)d_in[7];
    const float* bc = (const float*)d_in[8];
    float* out = (float*)d_out;

    float *hbuf = nullptr, *zbuf = nullptr;
    cudaGetSymbolAddress((void**)&hbuf, g_h);
    cudaGetSymbolAddress((void**)&zbuf, g_z);

    cudaFuncSetAttribute(mlp_kernel,
                         cudaFuncAttributeMaxDynamicSharedMemorySize, MLP_SMEM);

    const size_t featbytes = (size_t)NNODES * HID * sizeof(float);
    const int SC_BLOCKS  = NEDGES / 8;            // 8 warps/block, 1 edge/warp
    const int MLP_BLOCKS = (NNODES + 63) / 64;
    const int CLS_BLOCKS = (NNODES + 31) / 32;

    // layer 0: z = x + scatter(x); then MLP writes both h and z for layer 1
    cudaMemcpyAsync(zbuf, x, featbytes, cudaMemcpyDeviceToDevice);
    scatter_kernel<<<SC_BLOCKS, 256>>>(x, zbuf, ei);
    mlp_kernel<<<MLP_BLOCKS, 256, MLP_SMEM>>>(zbuf, hbuf, zbuf, W1, b1, W2, b2);

    for (int l = 1; l < NLAYERS; l++) {
        scatter_kernel<<<SC_BLOCKS, 256>>>(hbuf, zbuf, ei);
        mlp_kernel<<<MLP_BLOCKS, 256, MLP_SMEM>>>(
            zbuf, hbuf, zbuf,
            W1 + (size_t)l * HID * HID, b1 + (size_t)l * HID,
            W2 + (size_t)l * HID * HID, b2 + (size_t)l * HID);
    }

    cls_kernel<<<CLS_BLOCKS, 256>>>(hbuf, Wc, bc, out);
}

// round 5
// speedup vs baseline: 1.5517x; 1.5517x over previous
#include <cuda_runtime.h>

#define NNODES  50000
#define HID     128
#define NEDGES  600000
#define OUTC    40
#define NLAYERS 3

// Persistent scratch (allocation-free rule: __device__ globals).
__device__ float g_h[(size_t)NNODES * HID];
__device__ float g_z[(size_t)NNODES * HID];
__device__ int   g_deg[NNODES];
__device__ int   g_rowptr[NNODES + 1];
__device__ int   g_cur[NNODES];
__device__ int   g_col[NEDGES];

// ---------------- packed f32x2 helpers (sm_103a) ----------------
__device__ __forceinline__ unsigned long long pack2(float a, float b) {
    unsigned long long r;
    asm("mov.b64 %0, {%1,%2};" : "=l"(r) : "f"(a), "f"(b));
    return r;
}
__device__ __forceinline__ void unpack2(unsigned long long v, float& a, float& b) {
    asm("mov.b64 {%0,%1}, %2;" : "=f"(a), "=f"(b) : "l"(v));
}
__device__ __forceinline__ unsigned long long fma2(unsigned long long a,
                                                   unsigned long long b,
                                                   unsigned long long c) {
    unsigned long long d;
    asm("fma.rn.f32x2 %0, %1, %2, %3;" : "=l"(d) : "l"(a), "l"(b), "l"(c));
    return d;
}

// ================= CSR build (once per launch) =================
__global__ void count_kernel(const int* __restrict__ ei, int* __restrict__ deg) {
    int e = blockIdx.x * blockDim.x + threadIdx.x;
    if (e < NEDGES) atomicAdd(&deg[ei[NEDGES + e]], 1);
}

// Single-block shfl scan over 50000 degrees -> rowptr (inclusive shifted) + cur.
__global__ void scan_kernel(const int* __restrict__ deg,
                            int* __restrict__ rowptr, int* __restrict__ cur) {
    __shared__ int wsum[32];
    __shared__ int carry_s;
    int tid = threadIdx.x, lane = tid & 31, wid = tid >> 5;
    if (tid == 0) { carry_s = 0; rowptr[0] = 0; }
    __syncthreads();
    for (int base = 0; base < NNODES; base += 1024) {
        int i = base + tid;
        int v = (i < NNODES) ? deg[i] : 0;
        int s = v;
        #pragma unroll
        for (int o = 1; o < 32; o <<= 1) {
            int t = __shfl_up_sync(~0u, s, o);
            if (lane >= o) s += t;
        }
        if (lane == 31) wsum[wid] = s;
        __syncthreads();
        if (wid == 0) {
            int ws = wsum[lane];
            #pragma unroll
            for (int o = 1; o < 32; o <<= 1) {
                int t = __shfl_up_sync(~0u, ws, o);
                if (lane >= o) ws += t;
            }
            wsum[lane] = ws;
        }
        __syncthreads();
        int incl = carry_s + (wid > 0 ? wsum[wid - 1] : 0) + s;
        if (i < NNODES) { rowptr[i + 1] = incl; cur[i] = incl - v; }
        __syncthreads();
        if (tid == 1023) carry_s = incl;
        __syncthreads();
    }
}

__global__ void fill_kernel(const int* __restrict__ ei,
                            int* __restrict__ cur, int* __restrict__ col) {
    int e = blockIdx.x * blockDim.x + threadIdx.x;
    if (e >= NEDGES) return;
    int slot = atomicAdd(&cur[ei[NEDGES + e]], 1);
    col[slot] = ei[e];   // src
}

// ================= gather: z[d,:] = h[d,:] + sum_{s in N(d)} h[s,:] =========
// One warp per dst node; lane owns a float4 (512B row). Streaming z write
// replaces the 307MB of atomic red writes.
__global__ __launch_bounds__(256) void gather_kernel(
        const float* __restrict__ h, float* __restrict__ z,
        const int* __restrict__ rowptr, const int* __restrict__ col) {
    int node = (blockIdx.x * blockDim.x + threadIdx.x) >> 5;
    if (node >= NNODES) return;
    int lane = threadIdx.x & 31;
    int beg = rowptr[node], end = rowptr[node + 1];
    float4 acc = *(const float4*)(h + (size_t)node * HID + lane * 4);
    int j = beg;
    while (j < end) {
        int n = min(32, end - j);
        int myc = (lane < n) ? col[j + lane] : 0;
        for (int t = 0; t < n; t++) {
            int s = __shfl_sync(~0u, myc, t);
            float4 v = *(const float4*)(h + (size_t)s * HID + lane * 4);
            acc.x += v.x; acc.y += v.y; acc.z += v.z; acc.w += v.w;
        }
        j += n;
    }
    *(float4*)(z + (size_t)node * HID + lane * 4) = acc;
}

// ============ fused GIN MLP: h' = relu( relu(z@W1+b1)@W2 + b2 ) ============
// 128 threads, tile 128 rows x 128 cols, each thread 8 rows x 8 col-pairs
// (64 f32x2 accumulators). Per warp-k: 24 crossbar-cyc of LDS vs 32 fma-cyc
// -> fma-pipe bound. W staged in two 64-row chunks (32KB) so total smem
// ~99KB -> 2 CTAs/SM.
#define MLP_PAD  129
#define MLP_SMEM ((128 * MLP_PAD + 64 * HID + HID) * 4)

__global__ __launch_bounds__(128) void mlp_kernel(
        const float* __restrict__ zin, float* __restrict__ hout,
        const float* __restrict__ W1, const float* __restrict__ b1,
        const float* __restrict__ W2, const float* __restrict__ b2) {
    extern __shared__ float sm[];
    float* zs = sm;                       // [128][129]
    float* Ws = sm + 128 * MLP_PAD;       // [64][128] k-chunk
    float* bs = Ws + 64 * HID;            // [128]

    const int tid = threadIdx.x;
    const int tx = tid & 7;               // 8 col groups (8 pairs: c = 2tx+16q)
    const int ty = tid >> 3;              // 16 row groups (8 rows each)
    const int row0 = blockIdx.x * 128;
    const int rmax = NNODES - row0;

    // Stage z tile (float4 loads, scalar STS due to odd pad), W1 chunk0, b1.
    for (int i = tid; i < 128 * 32; i += 128) {
        int r = i >> 5, c4 = (i & 31) * 4;
        float4 v = (r < rmax) ? *(const float4*)(zin + (size_t)(row0 + r) * HID + c4)
                              : make_float4(0.f, 0.f, 0.f, 0.f);
        float* d = zs + r * MLP_PAD + c4;
        d[0] = v.x; d[1] = v.y; d[2] = v.z; d[3] = v.w;
    }
    for (int i = tid; i < 64 * HID / 4; i += 128)
        ((float4*)Ws)[i] = ((const float4*)W1)[i];
    bs[tid] = b1[tid];
    __syncthreads();

    unsigned long long acc[8][8];

    // ---- phase 1: hidden = relu(z @ W1 + b1) ----
    #pragma unroll
    for (int q = 0; q < 8; q++) {
        int c = 2 * tx + 16 * q;
        unsigned long long bq = pack2(bs[c], bs[c + 1]);
        #pragma unroll
        for (int i = 0; i < 8; i++) acc[i][q] = bq;
    }
    #pragma unroll 1
    for (int kc = 0; kc < 2; kc++) {
        #pragma unroll 2
        for (int kk = 0; kk < 64; kk++) {
            unsigned long long zp[8], wp[8];
            #pragma unroll
            for (int i = 0; i < 8; i++) {
                float v = zs[(ty * 8 + i) * MLP_PAD + kc * 64 + kk];
                zp[i] = pack2(v, v);
            }
            #pragma unroll
            for (int q = 0; q < 8; q++)
                wp[q] = *(const unsigned long long*)(Ws + kk * HID + 2 * tx + 16 * q);
            #pragma unroll
            for (int i = 0; i < 8; i++)
                #pragma unroll
                for (int q = 0; q < 8; q++)
                    acc[i][q] = fma2(zp[i], wp[q], acc[i][q]);
        }
        __syncthreads();
        if (kc == 0) {   // stage W1 chunk1
            for (int i = tid; i < 64 * HID / 4; i += 128)
                ((float4*)Ws)[i] = ((const float4*)(W1 + 64 * HID))[i];
            __syncthreads();
        }
    }

    // hidden (relu) -> zs ; stage W2 chunk0 + b2
    #pragma unroll
    for (int i = 0; i < 8; i++) {
        int r = ty * 8 + i;
        #pragma unroll
        for (int q = 0; q < 8; q++) {
            float a, b; unpack2(acc[i][q], a, b);
            int c = 2 * tx + 16 * q;
            zs[r * MLP_PAD + c]     = fmaxf(a, 0.f);
            zs[r * MLP_PAD + c + 1] = fmaxf(b, 0.f);
        }
    }
    for (int i = tid; i < 64 * HID / 4; i += 128)
        ((float4*)Ws)[i] = ((const float4*)W2)[i];
    bs[tid] = b2[tid];
    __syncthreads();

    // ---- phase 2: out = relu(hidden @ W2 + b2) ----
    #pragma unroll
    for (int q = 0; q < 8; q++) {
        int c = 2 * tx + 16 * q;
        unsigned long long bq = pack2(bs[c], bs[c + 1]);
        #pragma unroll
        for (int i = 0; i < 8; i++) acc[i][q] = bq;
    }
    #pragma unroll 1
    for (int kc = 0; kc < 2; kc++) {
        #pragma unroll 2
        for (int kk = 0; kk < 64; kk++) {
            unsigned long long zp[8], wp[8];
            #pragma unroll
            for (int i = 0; i < 8; i++) {
                float v = zs[(ty * 8 + i) * MLP_PAD + kc * 64 + kk];
                zp[i] = pack2(v, v);
            }
            #pragma unroll
            for (int q = 0; q < 8; q++)
                wp[q] = *(const unsigned long long*)(Ws + kk * HID + 2 * tx + 16 * q);
            #pragma unroll
            for (int i = 0; i < 8; i++)
                #pragma unroll
                for (int q = 0; q < 8; q++)
                    acc[i][q] = fma2(zp[i], wp[q], acc[i][q]);
        }
        __syncthreads();
        if (kc == 0) {   // stage W2 chunk1
            for (int i = tid; i < 64 * HID / 4; i += 128)
                ((float4*)Ws)[i] = ((const float4*)(W2 + 64 * HID))[i];
            __syncthreads();
        }
    }

    // epilogue: relu -> hout
    #pragma unroll
    for (int i = 0; i < 8; i++) {
        int r = ty * 8 + i;
        if (r < rmax) {
            #pragma unroll
            for (int q = 0; q < 8; q++) {
                float a, b; unpack2(acc[i][q], a, b);
                float2 o = make_float2(fmaxf(a, 0.f), fmaxf(b, 0.f));
                *(float2*)(hout + (size_t)(row0 + r) * HID + 2 * tx + 16 * q) = o;
            }
        }
    }
}

// ---------------- classifier: out = h @ Wc + bc ----------------
__global__ __launch_bounds__(256) void cls_kernel(
        const float* __restrict__ h, const float* __restrict__ Wc,
        const float* __restrict__ bc, float* __restrict__ out) {
    __shared__ float hs[32][129];
    __shared__ float Ws[HID * OUTC];
    __shared__ float bsc[OUTC];

    const int tid = threadIdx.x;
    const int row0 = blockIdx.x * 32;

    for (int i = tid; i < 32 * HID; i += 256) {
        int r = i >> 7, k = i & 127;
        hs[r][k] = (row0 + r < NNODES) ? h[(size_t)(row0 + r) * HID + k] : 0.f;
    }
    for (int i = tid; i < HID * OUTC; i += 256) Ws[i] = Wc[i];
    if (tid < OUTC) bsc[tid] = bc[tid];
    __syncthreads();

    const int ty = tid >> 3;   // row 0..31
    const int tx = tid & 7;    // cols tx*5 .. tx*5+4

    float acc[5];
    #pragma unroll
    for (int c = 0; c < 5; c++) acc[c] = bsc[tx * 5 + c];
    #pragma unroll 4
    for (int k = 0; k < HID; k++) {
        float hv = hs[ty][k];
        #pragma unroll
        for (int c = 0; c < 5; c++)
            acc[c] = fmaf(hv, Ws[k * OUTC + tx * 5 + c], acc[c]);
    }
    int r = row0 + ty;
    if (r < NNODES) {
        #pragma unroll
        for (int c = 0; c < 5; c++) out[(size_t)r * OUTC + tx * 5 + c] = acc[c];
    }
}

// ---------------- launch ----------------
extern "C" void kernel_launch(void* const* d_in, const int* in_sizes, int n_in,
                              void* d_out, int out_size) {
    (void)in_sizes; (void)n_in; (void)out_size;
    const float* x  = (const float*)d_in[0];
    // d_in[1] = edge_attr (unused)
    const int*   ei = (const int*)d_in[2];       // int32 (JAX demotes int64)
    const float* W1 = (const float*)d_in[3];
    const float* b1 = (const float*)d_in[4];
    const float* W2 = (const float*)d_in[5];
    const float* b2 = (const float*)d_in[6];
    const float* Wc = (const float*)d_in[7];
    const float* bc = (const float*)d_in[8];
    float* out = (float*)d_out;

    float *hbuf, *zbuf;
    int *deg, *rowptr, *cur, *col;
    cudaGetSymbolAddress((void**)&hbuf, g_h);
    cudaGetSymbolAddress((void**)&zbuf, g_z);
    cudaGetSymbolAddress((void**)&deg, g_deg);
    cudaGetSymbolAddress((void**)&rowptr, g_rowptr);
    cudaGetSymbolAddress((void**)&cur, g_cur);
    cudaGetSymbolAddress((void**)&col, g_col);

    cudaFuncSetAttribute(mlp_kernel,
                         cudaFuncAttributeMaxDynamicSharedMemorySize, MLP_SMEM);

    const int EB = (NEDGES + 255) / 256;
    const int GB = (NNODES * 32 + 255) / 256;       // gather: warp/node
    const int MB = (NNODES + 127) / 128;
    const int CB = (NNODES + 31) / 32;

    // --- CSR build (per launch; atomic fill order only perturbs fp low bits)
    cudaMemsetAsync(deg, 0, NNODES * sizeof(int));
    count_kernel<<<EB, 256>>>(ei, deg);
    scan_kernel<<<1, 1024>>>(deg, rowptr, cur);
    fill_kernel<<<EB, 256>>>(ei, cur, col);

    // --- layer 0 (h = x)
    gather_kernel<<<GB, 256>>>(x, zbuf, rowptr, col);
    mlp_kernel<<<MB, 128, MLP_SMEM>>>(zbuf, hbuf, W1, b1, W2, b2);

    for (int l = 1; l < NLAYERS; l++) {
        gather_kernel<<<GB, 256>>>(hbuf, zbuf, rowptr, col);
        mlp_kernel<<<MB, 128, MLP_SMEM>>>(
            zbuf, hbuf,
            W1 + (size_t)l * HID * HID, b1 + (size_t)l * HID,
            W2 + (size_t)l * HID * HID, b2 + (size_t)l * HID);
    }

    cls_kernel<<<CB, 256>>>(hbuf, Wc, bc, out);
}

// round 7
// speedup vs baseline: 1.8618x; 1.1999x over previous
#include <cuda_runtime.h>
#include <cuda_bf16.h>
#include <stdint.h>

#define NNODES  50000
#define HID     128
#define NEDGES  600000
#define OUTC    40
#define NLAYERS 3
#define NTILES  391            // ceil(50000/128)

// ---------------- persistent scratch (__device__ globals) ------------------
__device__ float g_h[(size_t)NNODES * HID];
__device__ __nv_bfloat16 g_zhi[(size_t)NTILES * 128 * HID];   // row-major split z
__device__ __nv_bfloat16 g_zlo[(size_t)NTILES * 128 * HID];
// per layer: [W1hi, W1lo, W2hi, W2lo], each W^T [n][k] row-major 128x128 bf16
__device__ __nv_bfloat16 g_wsp[(size_t)NLAYERS * 4 * HID * HID];
__device__ int g_deg[NNODES];
__device__ int g_rowptr[NNODES + 1];
__device__ int g_cur[NNODES];
__device__ int g_col[NEDGES];

// ---------------- mma.sync / ldmatrix (sm_80+ baseline, non-'a') -----------
__device__ __forceinline__ uint32_t smem_u32(const void* p) {
    uint32_t a;
    asm("{ .reg .u64 t; cvta.to.shared.u64 t, %1; cvt.u32.u64 %0, t; }"
        : "=r"(a) : "l"(p));
    return a;
}
__device__ __forceinline__ void ldsm_x4(uint32_t* r, uint32_t addr) {
    asm volatile("ldmatrix.sync.aligned.m8n8.x4.shared.b16 {%0,%1,%2,%3}, [%4];"
                 : "=r"(r[0]), "=r"(r[1]), "=r"(r[2]), "=r"(r[3]) : "r"(addr));
}
__device__ __forceinline__ void mma16816(float* c, const uint32_t* a, const uint32_t* b) {
    asm volatile(
        "mma.sync.aligned.m16n8k16.row.col.f32.bf16.bf16.f32 "
        "{%0,%1,%2,%3}, {%4,%5,%6,%7}, {%8,%9}, {%0,%1,%2,%3};"
        : "+f"(c[0]), "+f"(c[1]), "+f"(c[2]), "+f"(c[3])
        : "r"(a[0]), "r"(a[1]), "r"(a[2]), "r"(a[3]), "r"(b[0]), "r"(b[1]));
}
__device__ __forceinline__ uint32_t pack_bf16x2(float a, float b) {
    __nv_bfloat16 ha = __float2bfloat16(a), hb = __float2bfloat16(b);
    return (uint32_t)__bfloat16_as_ushort(ha) |
           ((uint32_t)__bfloat16_as_ushort(hb) << 16);
}

// ================= CSR build (validated) ===================================
__global__ void count_kernel(const int* __restrict__ ei, int* __restrict__ deg) {
    int e = blockIdx.x * blockDim.x + threadIdx.x;
    if (e < NEDGES) atomicAdd(&deg[ei[NEDGES + e]], 1);
}
__global__ void scan_kernel(const int* __restrict__ deg,
                            int* __restrict__ rowptr, int* __restrict__ cur) {
    __shared__ int wsum[32];
    __shared__ int carry_s;
    int tid = threadIdx.x, lane = tid & 31, wid = tid >> 5;
    if (tid == 0) { carry_s = 0; rowptr[0] = 0; }
    __syncthreads();
    for (int base = 0; base < NNODES; base += 1024) {
        int i = base + tid;
        int v = (i < NNODES) ? deg[i] : 0;
        int s = v;
        #pragma unroll
        for (int o = 1; o < 32; o <<= 1) {
            int t = __shfl_up_sync(~0u, s, o);
            if (lane >= o) s += t;
        }
        if (lane == 31) wsum[wid] = s;
        __syncthreads();
        if (wid == 0) {
            int ws = wsum[lane];
            #pragma unroll
            for (int o = 1; o < 32; o <<= 1) {
                int t = __shfl_up_sync(~0u, ws, o);
                if (lane >= o) ws += t;
            }
            wsum[lane] = ws;
        }
        __syncthreads();
        int incl = carry_s + (wid > 0 ? wsum[wid - 1] : 0) + s;
        if (i < NNODES) { rowptr[i + 1] = incl; cur[i] = incl - v; }
        __syncthreads();
        if (tid == 1023) carry_s = incl;
        __syncthreads();
    }
}
__global__ void fill_kernel(const int* __restrict__ ei,
                            int* __restrict__ cur, int* __restrict__ col) {
    int e = blockIdx.x * blockDim.x + threadIdx.x;
    if (e >= NEDGES) return;
    int slot = atomicAdd(&cur[ei[NEDGES + e]], 1);
    col[slot] = ei[e];
}

// ==== W pre-split: fp32 W[k,n] -> bf16 hi/lo W^T[n,k] row-major ===========
__global__ void wsplit_kernel(const float* __restrict__ W1,
                              const float* __restrict__ W2) {
    int i = blockIdx.x * blockDim.x + threadIdx.x;
    if (i >= NLAYERS * 2 * HID * HID) return;
    int e = i & (HID * HID - 1);
    int m = (i >> 14) & 1;           // 0 = W1, 1 = W2
    int l = i >> 15;                 // layer
    int k = e >> 7, n = e & 127;
    const float* W = (m ? W2 : W1) + (size_t)l * HID * HID;
    float v = W[k * HID + n];
    __nv_bfloat16 hi = __float2bfloat16(v);
    __nv_bfloat16 lo = __float2bfloat16(v - __bfloat162float(hi));
    __nv_bfloat16* base = g_wsp + ((size_t)l * 4 + m * 2) * HID * HID;
    base[n * HID + k] = hi;
    base[HID * HID + n * HID + k] = lo;
}

// ===== gather: z[d,:] = h[d,:] + sum_{s in N(d)} h[s,:] -> split bf16 ======
__global__ __launch_bounds__(256) void gather_kernel(
        const float* __restrict__ h,
        const int* __restrict__ rowptr, const int* __restrict__ col) {
    int node = (blockIdx.x * blockDim.x + threadIdx.x) >> 5;
    if (node >= NNODES) return;
    int lane = threadIdx.x & 31;
    int beg = rowptr[node], end = rowptr[node + 1];
    float4 acc = *(const float4*)(h + (size_t)node * HID + lane * 4);
    int j = beg;
    while (j < end) {
        int n = min(32, end - j);
        int myc = (lane < n) ? col[j + lane] : 0;
        for (int t = 0; t < n; t++) {
            int s = __shfl_sync(~0u, myc, t);
            float4 v = *(const float4*)(h + (size_t)s * HID + lane * 4);
            acc.x += v.x; acc.y += v.y; acc.z += v.z; acc.w += v.w;
        }
        j += n;
    }
    float f[4] = {acc.x, acc.y, acc.z, acc.w};
    uint32_t hw[2], lw[2];
    #pragma unroll
    for (int p = 0; p < 2; p++) {
        float v0 = f[2 * p], v1 = f[2 * p + 1];
        __nv_bfloat16 h0 = __float2bfloat16(v0), h1 = __float2bfloat16(v1);
        float r0 = v0 - __bfloat162float(h0), r1 = v1 - __bfloat162float(h1);
        hw[p] = (uint32_t)__bfloat16_as_ushort(h0) |
                ((uint32_t)__bfloat16_as_ushort(h1) << 16);
        lw[p] = pack_bf16x2(r0, r1);
    }
    size_t off = (size_t)node * HID + lane * 4;   // bf16 elements
    *(uint2*)((char*)g_zhi + off * 2) = make_uint2(hw[0], hw[1]);
    *(uint2*)((char*)g_zlo + off * 2) = make_uint2(lw[0], lw[1]);
}

// ===================== tensor-core fused GIN MLP (mma.sync) ================
// SMEM rows padded to 272B (17 x 16B) -> ldmatrix conflict-free, no swizzle.
#define SROW 272
#define ATB  (128 * SROW)              // 34816B per matrix tile
#define MLP_SMEM (4 * ATB + 1024)      // Ahi, Alo, Bhi, Blo, biases

__device__ __forceinline__ void stage_mat(char* dst, const uint4* src, int tid) {
    for (int i = tid; i < 2048; i += 256) {        // 128 rows x 16 uint4
        int row = i >> 4, ch = i & 15;
        *(uint4*)(dst + row * SROW + ch * 16) = src[i];
    }
}

// One GEMM phase: acc += sum of 3 split terms (Ahi*Bhi, Ahi*Blo, Alo*Bhi).
// aA/aB: this lane's ldmatrix base addresses into the hi tiles.
__device__ __forceinline__ void phase(float acc[16][4], uint32_t aA, uint32_t aB) {
    #pragma unroll 1
    for (int t = 0; t < 3; t++) {
        uint32_t aa = aA + ((t == 2) ? ATB : 0);
        uint32_t bb = aB + ((t == 1) ? ATB : 0);
        #pragma unroll 1
        for (int kc = 0; kc < 8; kc++) {
            uint32_t a[4];
            ldsm_x4(a, aa + kc * 32);
            #pragma unroll
            for (int jp = 0; jp < 8; jp++) {
                uint32_t b[4];
                ldsm_x4(b, bb + jp * 16 * SROW + kc * 32);
                mma16816(acc[2 * jp],     a, b);
                mma16816(acc[2 * jp + 1], a, b + 2);
            }
        }
    }
}

__global__ __launch_bounds__(256) void mlp_mma_kernel(
        float* __restrict__ hout, int layer,
        const float* __restrict__ b1, const float* __restrict__ b2) {
    extern __shared__ char sm[];
    char* ah = sm;
    char* al = sm + ATB;
    char* bh = sm + 2 * ATB;
    char* bl = sm + 3 * ATB;
    float* bs1 = (float*)(sm + 4 * ATB);
    float* bs2 = bs1 + HID;

    const int tid = threadIdx.x;
    const int warp = tid >> 5, lane = tid & 31;
    const int tile = blockIdx.x;
    const int row0 = tile * 128;
    const int rmax = NNODES - row0;

    // ---- stage A (split z) + W1^T (split) + biases ----
    stage_mat(ah, (const uint4*)((const char*)g_zhi + (size_t)tile * 32768), tid);
    stage_mat(al, (const uint4*)((const char*)g_zlo + (size_t)tile * 32768), tid);
    stage_mat(bh, (const uint4*)(g_wsp + ((size_t)layer * 4 + 0) * HID * HID), tid);
    stage_mat(bl, (const uint4*)(g_wsp + ((size_t)layer * 4 + 1) * HID * HID), tid);
    if (tid < HID) { bs1[tid] = b1[tid]; bs2[tid] = b2[tid]; }
    __syncthreads();

    // ldmatrix lane addressing
    const int rr = lane & 7, g = lane >> 3;
    const uint32_t aA = smem_u32(ah) + (warp * 16 + (g & 1) * 8 + rr) * SROW + (g >> 1) * 16;
    const uint32_t aB = smem_u32(bh) + ((g >> 1) * 8 + rr) * SROW + (g & 1) * 16;

    const int cl = (lane & 3) * 2;        // col within n-tile (pair)
    const int rl = lane >> 2;             // row within m16 (lo half)

    float acc[16][4];

    // ---- phase 1: hidden = relu(z @ W1 + b1) ----
    #pragma unroll
    for (int j = 0; j < 16; j++) {
        float v0 = bs1[8 * j + cl], v1 = bs1[8 * j + cl + 1];
        acc[j][0] = v0; acc[j][1] = v1; acc[j][2] = v0; acc[j][3] = v1;
    }
    phase(acc, aA, aB);

    // epilogue 1: relu + split -> back into A tiles (own warp's rows only)
    {
        int rowL = warp * 16 + rl, rowH = rowL + 8;
        #pragma unroll
        for (int j = 0; j < 16; j++) {
            int boff = 16 * j + (lane & 3) * 4;   // byte offset of col pair
            float v0 = fmaxf(acc[j][0], 0.f), v1 = fmaxf(acc[j][1], 0.f);
            float v2 = fmaxf(acc[j][2], 0.f), v3 = fmaxf(acc[j][3], 0.f);
            __nv_bfloat16 h0 = __float2bfloat16(v0), h1 = __float2bfloat16(v1);
            __nv_bfloat16 h2 = __float2bfloat16(v2), h3 = __float2bfloat16(v3);
            *(uint32_t*)(ah + rowL * SROW + boff) =
                (uint32_t)__bfloat16_as_ushort(h0) |
                ((uint32_t)__bfloat16_as_ushort(h1) << 16);
            *(uint32_t*)(ah + rowH * SROW + boff) =
                (uint32_t)__bfloat16_as_ushort(h2) |
                ((uint32_t)__bfloat16_as_ushort(h3) << 16);
            *(uint32_t*)(al + rowL * SROW + boff) =
                pack_bf16x2(v0 - __bfloat162float(h0), v1 - __bfloat162float(h1));
            *(uint32_t*)(al + rowH * SROW + boff) =
                pack_bf16x2(v2 - __bfloat162float(h2), v3 - __bfloat162float(h3));
        }
    }
    __syncthreads();

    // restage W2^T (split) into B tiles
    stage_mat(bh, (const uint4*)(g_wsp + ((size_t)layer * 4 + 2) * HID * HID), tid);
    stage_mat(bl, (const uint4*)(g_wsp + ((size_t)layer * 4 + 3) * HID * HID), tid);
    __syncthreads();

    // ---- phase 2: out = relu(hidden @ W2 + b2) ----
    #pragma unroll
    for (int j = 0; j < 16; j++) {
        float v0 = bs2[8 * j + cl], v1 = bs2[8 * j + cl + 1];
        acc[j][0] = v0; acc[j][1] = v1; acc[j][2] = v0; acc[j][3] = v1;
    }
    phase(acc, aA, aB);

    // epilogue 2: relu -> hout fp32
    {
        int rowL = warp * 16 + rl, rowH = rowL + 8;
        bool okL = rowL < rmax, okH = rowH < rmax;
        #pragma unroll
        for (int j = 0; j < 16; j++) {
            int c = 8 * j + cl;
            if (okL) {
                float2 o = make_float2(fmaxf(acc[j][0], 0.f), fmaxf(acc[j][1], 0.f));
                *(float2*)(hout + (size_t)(row0 + rowL) * HID + c) = o;
            }
            if (okH) {
                float2 o = make_float2(fmaxf(acc[j][2], 0.f), fmaxf(acc[j][3], 0.f));
                *(float2*)(hout + (size_t)(row0 + rowH) * HID + c) = o;
            }
        }
    }
}

// ---------------- classifier: out = h @ Wc + bc ----------------
__global__ __launch_bounds__(256) void cls_kernel(
        const float* __restrict__ h, const float* __restrict__ Wc,
        const float* __restrict__ bc, float* __restrict__ out) {
    __shared__ float hs[32][129];
    __shared__ float Ws[HID * OUTC];
    __shared__ float bsc[OUTC];

    const int tid = threadIdx.x;
    const int row0 = blockIdx.x * 32;

    for (int i = tid; i < 32 * HID; i += 256) {
        int rr = i >> 7, k = i & 127;
        hs[rr][k] = (row0 + rr < NNODES) ? h[(size_t)(row0 + rr) * HID + k] : 0.f;
    }
    for (int i = tid; i < HID * OUTC; i += 256) Ws[i] = Wc[i];
    if (tid < OUTC) bsc[tid] = bc[tid];
    __syncthreads();

    const int ty = tid >> 3;
    const int tx = tid & 7;

    float acc[5];
    #pragma unroll
    for (int c = 0; c < 5; c++) acc[c] = bsc[tx * 5 + c];
    #pragma unroll 4
    for (int k = 0; k < HID; k++) {
        float hv = hs[ty][k];
        #pragma unroll
        for (int c = 0; c < 5; c++)
            acc[c] = fmaf(hv, Ws[k * OUTC + tx * 5 + c], acc[c]);
    }
    int rr = row0 + ty;
    if (rr < NNODES) {
        #pragma unroll
        for (int c = 0; c < 5; c++) out[(size_t)rr * OUTC + tx * 5 + c] = acc[c];
    }
}

// ---------------- launch ----------------
extern "C" void kernel_launch(void* const* d_in, const int* in_sizes, int n_in,
                              void* d_out, int out_size) {
    (void)in_sizes; (void)n_in; (void)out_size;
    const float* x  = (const float*)d_in[0];
    const int*   ei = (const int*)d_in[2];       // int32 (JAX demotes int64)
    const float* W1 = (const float*)d_in[3];
    const float* b1 = (const float*)d_in[4];
    const float* W2 = (const float*)d_in[5];
    const float* b2 = (const float*)d_in[6];
    const float* Wc = (const float*)d_in[7];
    const float* bc = (const float*)d_in[8];
    float* out = (float*)d_out;

    float* hbuf;
    int *deg, *rowptr, *cur, *col;
    cudaGetSymbolAddress((void**)&hbuf, g_h);
    cudaGetSymbolAddress((void**)&deg, g_deg);
    cudaGetSymbolAddress((void**)&rowptr, g_rowptr);
    cudaGetSymbolAddress((void**)&cur, g_cur);
    cudaGetSymbolAddress((void**)&col, g_col);

    cudaFuncSetAttribute(mlp_mma_kernel,
                         cudaFuncAttributeMaxDynamicSharedMemorySize, MLP_SMEM);

    const int EB = (NEDGES + 255) / 256;
    const int GB = (NNODES * 32 + 255) / 256;
    const int WB = (NLAYERS * 2 * HID * HID + 255) / 256;
    const int CB = (NNODES + 31) / 32;

    // weight split/transpose (independent of graph data)
    wsplit_kernel<<<WB, 256>>>(W1, W2);

    // CSR build
    cudaMemsetAsync(deg, 0, NNODES * sizeof(int));
    count_kernel<<<EB, 256>>>(ei, deg);
    scan_kernel<<<1, 1024>>>(deg, rowptr, cur);
    fill_kernel<<<EB, 256>>>(ei, cur, col);

    // layer 0 (h = x)
    gather_kernel<<<GB, 256>>>(x, rowptr, col);
    mlp_mma_kernel<<<NTILES, 256, MLP_SMEM>>>(hbuf, 0, b1, b2);

    for (int l = 1; l < NLAYERS; l++) {
        gather_kernel<<<GB, 256>>>(hbuf, rowptr, col);
        mlp_mma_kernel<<<NTILES, 256, MLP_SMEM>>>(
            hbuf, l, b1 + (size_t)l * HID, b2 + (size_t)l * HID);
    }

    cls_kernel<<<CB, 256>>>(hbuf, Wc, bc, out);
}

// round 9
// speedup vs baseline: 2.1274x; 1.1426x over previous
#include <cuda_runtime.h>
#include <cuda_bf16.h>
#include <stdint.h>

#define NNODES  50000
#define HID     128
#define NEDGES  600000
#define OUTC    40
#define NLAYERS 3
#define NTILES  391            // ceil(50000/128)

// ---------------- persistent scratch (__device__ globals, zero-init) -------
__device__ float g_h[(size_t)NNODES * HID];
__device__ __nv_bfloat16 g_zhi[(size_t)NTILES * 128 * HID];   // row-major split z
__device__ __nv_bfloat16 g_zlo[(size_t)NTILES * 128 * HID];
// per layer: [W1hi, W1lo, W2hi, W2lo], each W^T [n][k] row-major 128x128 bf16
__device__ __nv_bfloat16 g_wsp[(size_t)NLAYERS * 4 * HID * HID];
// Wc^T padded to [64][128], hi then lo (pad rows never written -> stay zero)
__device__ __nv_bfloat16 g_wc[2 * 64 * HID];
__device__ int g_deg[NNODES];
__device__ int g_rowptr[NNODES + 1];
__device__ int g_cur[NNODES];
__device__ int g_col[NEDGES];

// ---------------- mma.sync / ldmatrix (sm_80+ baseline, non-'a') -----------
__device__ __forceinline__ uint32_t smem_u32(const void* p) {
    uint32_t a;
    asm("{ .reg .u64 t; cvta.to.shared.u64 t, %1; cvt.u32.u64 %0, t; }"
        : "=r"(a) : "l"(p));
    return a;
}
__device__ __forceinline__ void ldsm_x4(uint32_t* r, uint32_t addr) {
    asm volatile("ldmatrix.sync.aligned.m8n8.x4.shared.b16 {%0,%1,%2,%3}, [%4];"
                 : "=r"(r[0]), "=r"(r[1]), "=r"(r[2]), "=r"(r[3]) : "r"(addr));
}
__device__ __forceinline__ void mma16816(float* c, const uint32_t* a, const uint32_t* b) {
    asm volatile(
        "mma.sync.aligned.m16n8k16.row.col.f32.bf16.bf16.f32 "
        "{%0,%1,%2,%3}, {%4,%5,%6,%7}, {%8,%9}, {%0,%1,%2,%3};"
        : "+f"(c[0]), "+f"(c[1]), "+f"(c[2]), "+f"(c[3])
        : "r"(a[0]), "r"(a[1]), "r"(a[2]), "r"(a[3]), "r"(b[0]), "r"(b[1]));
}
__device__ __forceinline__ uint32_t pack_bf16x2(float a, float b) {
    __nv_bfloat16 ha = __float2bfloat16(a), hb = __float2bfloat16(b);
    return (uint32_t)__bfloat16_as_ushort(ha) |
           ((uint32_t)__bfloat16_as_ushort(hb) << 16);
}

// ================= CSR build ===============================================
__global__ void count_kernel(const int* __restrict__ ei, int* __restrict__ deg) {
    int e = blockIdx.x * blockDim.x + threadIdx.x;
    if (e < NEDGES) atomicAdd(&deg[ei[NEDGES + e]], 1);
}
// 4 values per thread per iteration (int4), single block of 1024.
__global__ void scan_kernel(const int* __restrict__ deg,
                            int* __restrict__ rowptr, int* __restrict__ cur) {
    __shared__ int wsum[32];
    __shared__ int carry_s;
    int tid = threadIdx.x, lane = tid & 31, wid = tid >> 5;
    if (tid == 0) { carry_s = 0; rowptr[0] = 0; }
    __syncthreads();
    const int NI4 = NNODES / 4;                  // 12500
    for (int base = 0; base < NI4; base += 1024) {
        int i4 = base + tid;
        int4 v = (i4 < NI4) ? ((const int4*)deg)[i4] : make_int4(0, 0, 0, 0);
        int local = v.x + v.y + v.z + v.w;
        int s = local;
        #pragma unroll
        for (int o = 1; o < 32; o <<= 1) {
            int t = __shfl_up_sync(~0u, s, o);
            if (lane >= o) s += t;
        }
        if (lane == 31) wsum[wid] = s;
        __syncthreads();
        if (wid == 0) {
            int ws = wsum[lane];
            #pragma unroll
            for (int o = 1; o < 32; o <<= 1) {
                int t = __shfl_up_sync(~0u, ws, o);
                if (lane >= o) ws += t;
            }
            wsum[lane] = ws;
        }
        __syncthreads();
        int incl = carry_s + (wid > 0 ? wsum[wid - 1] : 0) + s;
        if (i4 < NI4) {
            int excl = incl - local;
            int idx = i4 * 4;
            int p0 = excl + v.x, p1 = p0 + v.y, p2 = p1 + v.z, p3 = p2 + v.w;
            cur[idx] = excl; cur[idx + 1] = p0; cur[idx + 2] = p1; cur[idx + 3] = p2;
            rowptr[idx + 1] = p0; rowptr[idx + 2] = p1;
            rowptr[idx + 3] = p2; rowptr[idx + 4] = p3;
        }
        __syncthreads();
        if (tid == 1023) carry_s = incl;
        __syncthreads();
    }
}
__global__ void fill_kernel(const int* __restrict__ ei,
                            int* __restrict__ cur, int* __restrict__ col) {
    int e = blockIdx.x * blockDim.x + threadIdx.x;
    if (e >= NEDGES) return;
    int slot = atomicAdd(&cur[ei[NEDGES + e]], 1);
    col[slot] = ei[e];
}

// ==== W pre-split: fp32 W[k,n] -> bf16 hi/lo W^T[n,k] row-major ============
__global__ void wsplit_kernel(const float* __restrict__ W1,
                              const float* __restrict__ W2) {
    int i = blockIdx.x * blockDim.x + threadIdx.x;
    if (i >= NLAYERS * 2 * HID * HID) return;
    int e = i & (HID * HID - 1);
    int m = (i >> 14) & 1;           // 0 = W1, 1 = W2
    int l = i >> 15;                 // layer
    int k = e >> 7, n = e & 127;
    const float* W = (m ? W2 : W1) + (size_t)l * HID * HID;
    float v = W[k * HID + n];
    __nv_bfloat16 hi = __float2bfloat16(v);
    __nv_bfloat16 lo = __float2bfloat16(v - __bfloat162float(hi));
    __nv_bfloat16* base = g_wsp + ((size_t)l * 4 + m * 2) * HID * HID;
    base[n * HID + k] = hi;
    base[HID * HID + n * HID + k] = lo;
}
__global__ void wsplit_c_kernel(const float* __restrict__ Wc) {
    int i = blockIdx.x * blockDim.x + threadIdx.x;
    if (i >= OUTC * HID) return;
    int n = i / HID, k = i - n * HID;
    float v = Wc[k * OUTC + n];
    __nv_bfloat16 hi = __float2bfloat16(v);
    __nv_bfloat16 lo = __float2bfloat16(v - __bfloat162float(hi));
    g_wc[n * HID + k] = hi;
    g_wc[64 * HID + n * HID + k] = lo;
}

// ===== gather: z[d,:] = h[d,:] + sum_{s in N(d)} h[s,:] -> split bf16 ======
__global__ __launch_bounds__(256) void gather_kernel(
        const float* __restrict__ h,
        const int* __restrict__ rowptr, const int* __restrict__ col) {
    int node = (blockIdx.x * blockDim.x + threadIdx.x) >> 5;
    if (node >= NNODES) return;
    int lane = threadIdx.x & 31;
    int beg = rowptr[node], end = rowptr[node + 1];
    float4 acc = *(const float4*)(h + (size_t)node * HID + lane * 4);
    int j = beg;
    while (j < end) {
        int n = min(32, end - j);
        int myc = (lane < n) ? col[j + lane] : 0;
        int t = 0;
        for (; t + 3 < n; t += 4) {   // 4-way MLP on the dependent L2 loads
            int s0 = __shfl_sync(~0u, myc, t);
            int s1 = __shfl_sync(~0u, myc, t + 1);
            int s2 = __shfl_sync(~0u, myc, t + 2);
            int s3 = __shfl_sync(~0u, myc, t + 3);
            float4 v0 = *(const float4*)(h + (size_t)s0 * HID + lane * 4);
            float4 v1 = *(const float4*)(h + (size_t)s1 * HID + lane * 4);
            float4 v2 = *(const float4*)(h + (size_t)s2 * HID + lane * 4);
            float4 v3 = *(const float4*)(h + (size_t)s3 * HID + lane * 4);
            acc.x += (v0.x + v1.x) + (v2.x + v3.x);
            acc.y += (v0.y + v1.y) + (v2.y + v3.y);
            acc.z += (v0.z + v1.z) + (v2.z + v3.z);
            acc.w += (v0.w + v1.w) + (v2.w + v3.w);
        }
        for (; t < n; t++) {
            int s = __shfl_sync(~0u, myc, t);
            float4 v = *(const float4*)(h + (size_t)s * HID + lane * 4);
            acc.x += v.x; acc.y += v.y; acc.z += v.z; acc.w += v.w;
        }
        j += n;
    }
    float f[4] = {acc.x, acc.y, acc.z, acc.w};
    uint32_t hw[2], lw[2];
    #pragma unroll
    for (int p = 0; p < 2; p++) {
        float v0 = f[2 * p], v1 = f[2 * p + 1];
        __nv_bfloat16 h0 = __float2bfloat16(v0), h1 = __float2bfloat16(v1);
        hw[p] = (uint32_t)__bfloat16_as_ushort(h0) |
                ((uint32_t)__bfloat16_as_ushort(h1) << 16);
        lw[p] = pack_bf16x2(v0 - __bfloat162float(h0), v1 - __bfloat162float(h1));
    }
    size_t off = (size_t)node * HID + lane * 4;   // bf16 elements
    *(uint2*)((char*)g_zhi + off * 2) = make_uint2(hw[0], hw[1]);
    *(uint2*)((char*)g_zlo + off * 2) = make_uint2(lw[0], lw[1]);
}

// ===================== tensor-core fused GIN MLP (mma.sync) ================
// SMEM rows padded to 272B (17 x 16B) -> ldmatrix conflict-free.
// Layout: Ahi, Alo, B1hi, B1lo, B2hi, B2lo (6 x 34816B) + biases.
#define SROW 272
#define ATB  (128 * SROW)
#define MLP_SMEM (6 * ATB + 1536)

__device__ __forceinline__ void stage_mat(char* dst, const uint4* src,
                                          int tid, int nrow) {
    for (int i = tid; i < nrow * 16; i += 256) {
        int row = i >> 4, ch = i & 15;
        *(uint4*)(dst + row * SROW + ch * 16) = src[i];
    }
}

// One GEMM phase: acc += Ahi*Bhi + Ahi*Blo + Alo*Bhi (split terms).
template <int NJP>
__device__ __forceinline__ void phase(float (*acc)[4], uint32_t aA, uint32_t aB) {
    #pragma unroll 1
    for (int t = 0; t < 3; t++) {
        uint32_t aa = aA + ((t == 2) ? ATB : 0);
        uint32_t bb = aB + ((t == 1) ? ATB : 0);
        #pragma unroll
        for (int kc = 0; kc < 8; kc++) {
            uint32_t a[4];
            ldsm_x4(a, aa + kc * 32);
            #pragma unroll
            for (int jp = 0; jp < NJP; jp++) {
                uint32_t b[4];
                ldsm_x4(b, bb + jp * 16 * SROW + kc * 32);
                mma16816(acc[2 * jp],     a, b);
                mma16816(acc[2 * jp + 1], a, b + 2);
            }
        }
    }
}

// relu + hi/lo split of acc back into the A tiles (warp-local rows).
__device__ __forceinline__ void epi_to_smem(float (*acc)[4], char* ah, char* al,
                                            int warp, int lane) {
    int rl = lane >> 2;
    int rowL = warp * 16 + rl, rowH = rowL + 8;
    #pragma unroll
    for (int j = 0; j < 16; j++) {
        int boff = 16 * j + (lane & 3) * 4;
        float v0 = fmaxf(acc[j][0], 0.f), v1 = fmaxf(acc[j][1], 0.f);
        float v2 = fmaxf(acc[j][2], 0.f), v3 = fmaxf(acc[j][3], 0.f);
        __nv_bfloat16 h0 = __float2bfloat16(v0), h1 = __float2bfloat16(v1);
        __nv_bfloat16 h2 = __float2bfloat16(v2), h3 = __float2bfloat16(v3);
        *(uint32_t*)(ah + rowL * SROW + boff) =
            (uint32_t)__bfloat16_as_ushort(h0) |
            ((uint32_t)__bfloat16_as_ushort(h1) << 16);
        *(uint32_t*)(ah + rowH * SROW + boff) =
            (uint32_t)__bfloat16_as_ushort(h2) |
            ((uint32_t)__bfloat16_as_ushort(h3) << 16);
        *(uint32_t*)(al + rowL * SROW + boff) =
            pack_bf16x2(v0 - __bfloat162float(h0), v1 - __bfloat162float(h1));
        *(uint32_t*)(al + rowH * SROW + boff) =
            pack_bf16x2(v2 - __bfloat162float(h2), v3 - __bfloat162float(h3));
    }
}

__global__ __launch_bounds__(256) void mlp_mma_kernel(
        float* __restrict__ hout, int layer, int last,
        const float* __restrict__ b1, const float* __restrict__ b2,
        const float* __restrict__ bc, float* __restrict__ out) {
    extern __shared__ char sm[];
    char* ah = sm;
    char* al = sm + ATB;
    char* b1h = sm + 2 * ATB;          // also Wc slot for last layer
    char* b2h = sm + 4 * ATB;
    float* bs1 = (float*)(sm + 6 * ATB);
    float* bs2 = bs1 + HID;
    float* bs3 = bs2 + HID;            // 64 floats (bc padded)

    const int tid = threadIdx.x;
    const int warp = tid >> 5, lane = tid & 31;
    const int tile = blockIdx.x;
    const int row0 = tile * 128;
    const int rmax = NNODES - row0;

    // ---- stage A (split z) + W1^T + W2^T (split) + biases ----
    stage_mat(ah,  (const uint4*)((const char*)g_zhi + (size_t)tile * 32768), tid, 128);
    stage_mat(al,  (const uint4*)((const char*)g_zlo + (size_t)tile * 32768), tid, 128);
    stage_mat(b1h, (const uint4*)(g_wsp + ((size_t)layer * 4 + 0) * HID * HID), tid, 128);
    stage_mat(b1h + ATB, (const uint4*)(g_wsp + ((size_t)layer * 4 + 1) * HID * HID), tid, 128);
    stage_mat(b2h, (const uint4*)(g_wsp + ((size_t)layer * 4 + 2) * HID * HID), tid, 128);
    stage_mat(b2h + ATB, (const uint4*)(g_wsp + ((size_t)layer * 4 + 3) * HID * HID), tid, 128);
    if (tid < HID) { bs1[tid] = b1[tid]; bs2[tid] = b2[tid]; }
    if (tid < 64)  bs3[tid] = (tid < OUTC) ? bc[tid] : 0.f;
    __syncthreads();

    // ldmatrix lane addressing
    const int rr = lane & 7, g = lane >> 3;
    const uint32_t aA = smem_u32(ah) +
        (warp * 16 + (g & 1) * 8 + rr) * SROW + (g >> 1) * 16;
    const uint32_t bOff = ((g >> 1) * 8 + rr) * SROW + (g & 1) * 16;
    const uint32_t aB1 = smem_u32(b1h) + bOff;
    const uint32_t aB2 = smem_u32(b2h) + bOff;

    const int cl = (lane & 3) * 2;
    const int rl = lane >> 2;

    float acc[16][4];

    // ---- phase 1: hidden = relu(z @ W1 + b1) ----
    #pragma unroll
    for (int j = 0; j < 16; j++) {
        float v0 = bs1[8 * j + cl], v1 = bs1[8 * j + cl + 1];
        acc[j][0] = v0; acc[j][1] = v1; acc[j][2] = v0; acc[j][3] = v1;
    }
    phase<8>(acc, aA, aB1);
    epi_to_smem(acc, ah, al, warp, lane);   // warp-local rows only

    if (last) {
        __syncthreads();                     // phase-1 B1 reads done everywhere
        stage_mat(b1h, (const uint4*)g_wc, tid, 64);            // Wc hi
        stage_mat(b1h + ATB, (const uint4*)(g_wc + 64 * HID), tid, 64);  // Wc lo
        __syncthreads();
    } else {
        __syncwarp();                        // A rewrite is warp-local; B2 untouched
    }

    // ---- phase 2: hfin = relu(hidden @ W2 + b2) ----
    #pragma unroll
    for (int j = 0; j < 16; j++) {
        float v0 = bs2[8 * j + cl], v1 = bs2[8 * j + cl + 1];
        acc[j][0] = v0; acc[j][1] = v1; acc[j][2] = v0; acc[j][3] = v1;
    }
    phase<8>(acc, aA, aB2);

    if (!last) {
        // epilogue: relu -> hout fp32
        int rowL = warp * 16 + rl, rowH = rowL + 8;
        bool okL = rowL < rmax, okH = rowH < rmax;
        #pragma unroll
        for (int j = 0; j < 16; j++) {
            int c = 8 * j + cl;
            if (okL) {
                float2 o = make_float2(fmaxf(acc[j][0], 0.f), fmaxf(acc[j][1], 0.f));
                *(float2*)(hout + (size_t)(row0 + rowL) * HID + c) = o;
            }
            if (okH) {
                float2 o = make_float2(fmaxf(acc[j][2], 0.f), fmaxf(acc[j][3], 0.f));
                *(float2*)(hout + (size_t)(row0 + rowH) * HID + c) = o;
            }
        }
        return;
    }

    // ---- last layer: keep hfin in SMEM, fused classifier phase ----
    epi_to_smem(acc, ah, al, warp, lane);
    __syncwarp();

    float acc3[8][4];
    #pragma unroll
    for (int j = 0; j < 8; j++) {
        float v0 = bs3[8 * j + cl], v1 = bs3[8 * j + cl + 1];
        acc3[j][0] = v0; acc3[j][1] = v1; acc3[j][2] = v0; acc3[j][3] = v1;
    }
    phase<4>(acc3, aA, aB1);   // B1 slots now hold Wc (split), n = 64

    {
        int rowL = warp * 16 + rl, rowH = rowL + 8;
        bool okL = rowL < rmax, okH = rowH < rmax;
        #pragma unroll
        for (int j = 0; j < 5; j++) {        // cols 0..39 (pairs up to 38/39)
            int c = 8 * j + cl;
            if (okL) {
                float2 o = make_float2(acc3[j][0], acc3[j][1]);
                *(float2*)(out + (size_t)(row0 + rowL) * OUTC + c) = o;
            }
            if (okH) {
                float2 o = make_float2(acc3[j][2], acc3[j][3]);
                *(float2*)(out + (size_t)(row0 + rowH) * OUTC + c) = o;
            }
        }
    }
}

// ---------------- launch ----------------
extern "C" void kernel_launch(void* const* d_in, const int* in_sizes, int n_in,
                              void* d_out, int out_size) {
    (void)in_sizes; (void)n_in; (void)out_size;
    const float* x  = (const float*)d_in[0];
    const int*   ei = (const int*)d_in[2];       // int32 (JAX demotes int64)
    const float* W1 = (const float*)d_in[3];
    const float* b1 = (const float*)d_in[4];
    const float* W2 = (const float*)d_in[5];
    const float* b2 = (const float*)d_in[6];
    const float* Wc = (const float*)d_in[7];
    const float* bc = (const float*)d_in[8];
    float* out = (float*)d_out;

    float* hbuf;
    int *deg, *rowptr, *cur, *col;
    cudaGetSymbolAddress((void**)&hbuf, g_h);
    cudaGetSymbolAddress((void**)&deg, g_deg);
    cudaGetSymbolAddress((void**)&rowptr, g_rowptr);
    cudaGetSymbolAddress((void**)&cur, g_cur);
    cudaGetSymbolAddress((void**)&col, g_col);

    cudaFuncSetAttribute(mlp_mma_kernel,
                         cudaFuncAttributeMaxDynamicSharedMemorySize, MLP_SMEM);

    const int EB = (NEDGES + 255) / 256;
    const int GB = (NNODES * 32 + 255) / 256;
    const int WB = (NLAYERS * 2 * HID * HID + 255) / 256;

    // weight split/transpose
    wsplit_kernel<<<WB, 256>>>(W1, W2);
    wsplit_c_kernel<<<(OUTC * HID + 255) / 256, 256>>>(Wc);

    // CSR build
    cudaMemsetAsync(deg, 0, NNODES * sizeof(int));
    count_kernel<<<EB, 256>>>(ei, deg);
    scan_kernel<<<1, 1024>>>(deg, rowptr, cur);
    fill_kernel<<<EB, 256>>>(ei, cur, col);

    // layer 0 (h = x)
    gather_kernel<<<GB, 256>>>(x, rowptr, col);
    mlp_mma_kernel<<<NTILES, 256, MLP_SMEM>>>(hbuf, 0, 0, b1, b2, bc, out);

    for (int l = 1; l < NLAYERS; l++) {
        gather_kernel<<<GB, 256>>>(hbuf, rowptr, col);
        mlp_mma_kernel<<<NTILES, 256, MLP_SMEM>>>(
            hbuf, l, (l == NLAYERS - 1) ? 1 : 0,
            b1 + (size_t)l * HID, b2 + (size_t)l * HID, bc, out);
    }
}

// round 10
// speedup vs baseline: 2.1567x; 1.0138x over previous
#include <cuda_runtime.h>
#include <cuda_bf16.h>
#include <stdint.h>

#define NNODES  50000
#define HID     128
#define NEDGES  600000
#define OUTC    40
#define NLAYERS 3
#define NTILES  391            // ceil(50000/128)
#define SCB     49             // ceil(50000/1024) scan blocks

// ---------------- persistent scratch (__device__ globals, zero-init) -------
__device__ float g_h[(size_t)NNODES * HID];
__device__ __nv_bfloat16 g_zhi[(size_t)NTILES * 128 * HID];   // row-major split z
__device__ __nv_bfloat16 g_zlo[(size_t)NTILES * 128 * HID];
// per layer: [W1hi, W1lo, W2hi, W2lo], each W^T [n][k] row-major 128x128 bf16
__device__ __nv_bfloat16 g_wsp[(size_t)NLAYERS * 4 * HID * HID];
// Wc^T padded to [64][128], hi then lo (pad rows never written -> stay zero)
__device__ __nv_bfloat16 g_wc[2 * 64 * HID];
__device__ int g_deg[NNODES];
__device__ int g_rowptr[NNODES + 1];
__device__ int g_cur[NNODES];
__device__ int g_col[NEDGES];
__device__ int g_bsum[SCB];

// ---------------- mma.sync / ldmatrix (sm_80+ baseline, non-'a') -----------
__device__ __forceinline__ uint32_t smem_u32(const void* p) {
    uint32_t a;
    asm("{ .reg .u64 t; cvta.to.shared.u64 t, %1; cvt.u32.u64 %0, t; }"
        : "=r"(a) : "l"(p));
    return a;
}
__device__ __forceinline__ void ldsm_x4(uint32_t* r, uint32_t addr) {
    asm volatile("ldmatrix.sync.aligned.m8n8.x4.shared.b16 {%0,%1,%2,%3}, [%4];"
                 : "=r"(r[0]), "=r"(r[1]), "=r"(r[2]), "=r"(r[3]) : "r"(addr));
}
__device__ __forceinline__ void mma16816(float* c, const uint32_t* a, const uint32_t* b) {
    asm volatile(
        "mma.sync.aligned.m16n8k16.row.col.f32.bf16.bf16.f32 "
        "{%0,%1,%2,%3}, {%4,%5,%6,%7}, {%8,%9}, {%0,%1,%2,%3};"
        : "+f"(c[0]), "+f"(c[1]), "+f"(c[2]), "+f"(c[3])
        : "r"(a[0]), "r"(a[1]), "r"(a[2]), "r"(a[3]), "r"(b[0]), "r"(b[1]));
}
__device__ __forceinline__ uint32_t pack_bf16x2(float a, float b) {
    __nv_bfloat16 ha = __float2bfloat16(a), hb = __float2bfloat16(b);
    return (uint32_t)__bfloat16_as_ushort(ha) |
           ((uint32_t)__bfloat16_as_ushort(hb) << 16);
}

// ================= CSR build ===============================================
__global__ void count_kernel(const int* __restrict__ ei, int* __restrict__ deg) {
    int e = blockIdx.x * blockDim.x + threadIdx.x;
    if (e < NEDGES) atomicAdd(&deg[ei[NEDGES + e]], 1);
}

// -- pass 1: per-block sums (49 blocks x 256 threads x int4 = 1024 elems) ---
__global__ __launch_bounds__(256) void bsum_kernel(const int* __restrict__ deg,
                                                   int* __restrict__ bsum) {
    __shared__ int ws[8];
    int tid = threadIdx.x, lane = tid & 31, wid = tid >> 5;
    int i4 = blockIdx.x * 256 + tid;
    int s = 0;
    if (i4 < NNODES / 4) {
        int4 v = ((const int4*)deg)[i4];
        s = (v.x + v.y) + (v.z + v.w);
    }
    #pragma unroll
    for (int o = 16; o > 0; o >>= 1) s += __shfl_down_sync(~0u, s, o);
    if (lane == 0) ws[wid] = s;
    __syncthreads();
    if (wid == 0) {
        int t = (lane < 8) ? ws[lane] : 0;
        #pragma unroll
        for (int o = 4; o > 0; o >>= 1) t += __shfl_down_sync(~0u, t, o);
        if (lane == 0) bsum[blockIdx.x] = t;
    }
}

// -- pass 2: exclusive scan of 49 block sums (single 64-thread block) -------
__global__ void bscan_kernel(int* __restrict__ bsum) {
    __shared__ int w0;
    int tid = threadIdx.x, lane = tid & 31, wid = tid >> 5;
    int v = (tid < SCB) ? bsum[tid] : 0;
    int s = v;
    #pragma unroll
    for (int o = 1; o < 32; o <<= 1) {
        int t = __shfl_up_sync(~0u, s, o);
        if (lane >= o) s += t;
    }
    if (wid == 0 && lane == 31) w0 = s;
    __syncthreads();
    int incl = s + (wid ? w0 : 0);
    if (tid < SCB) bsum[tid] = incl - v;   // exclusive
}

// -- pass 3: rescan chunks with block offset, emit rowptr + cur -------------
__global__ __launch_bounds__(256) void scan2_kernel(
        const int* __restrict__ deg, const int* __restrict__ bsum,
        int* __restrict__ rowptr, int* __restrict__ cur) {
    __shared__ int ws[8];
    int tid = threadIdx.x, lane = tid & 31, wid = tid >> 5;
    int i4 = blockIdx.x * 256 + tid;
    int4 v = make_int4(0, 0, 0, 0);
    if (i4 < NNODES / 4) v = ((const int4*)deg)[i4];
    int local = (v.x + v.y) + (v.z + v.w);
    int s = local;
    #pragma unroll
    for (int o = 1; o < 32; o <<= 1) {
        int t = __shfl_up_sync(~0u, s, o);
        if (lane >= o) s += t;
    }
    if (lane == 31) ws[wid] = s;
    __syncthreads();
    if (wid == 0) {
        int t = (lane < 8) ? ws[lane] : 0;
        #pragma unroll
        for (int o = 1; o < 8; o <<= 1) {
            int u = __shfl_up_sync(~0u, t, o);
            if (lane >= o) t += u;
        }
        if (lane < 8) ws[lane] = t;
    }
    __syncthreads();
    int excl = bsum[blockIdx.x] + (wid ? ws[wid - 1] : 0) + (s - local);
    if (i4 < NNODES / 4) {
        int idx = i4 * 4;
        int p0 = excl + v.x, p1 = p0 + v.y, p2 = p1 + v.z, p3 = p2 + v.w;
        cur[idx] = excl; cur[idx + 1] = p0; cur[idx + 2] = p1; cur[idx + 3] = p2;
        rowptr[idx + 1] = p0; rowptr[idx + 2] = p1;
        rowptr[idx + 3] = p2; rowptr[idx + 4] = p3;
    }
    if (blockIdx.x == 0 && tid == 0) rowptr[0] = 0;
}

__global__ void fill_kernel(const int* __restrict__ ei,
                            int* __restrict__ cur, int* __restrict__ col) {
    int e = blockIdx.x * blockDim.x + threadIdx.x;
    if (e >= NEDGES) return;
    int slot = atomicAdd(&cur[ei[NEDGES + e]], 1);
    col[slot] = ei[e];
}

// ==== W pre-split: fp32 W[k,n] -> bf16 hi/lo W^T[n,k] row-major ============
__global__ void wsplit_kernel(const float* __restrict__ W1,
                              const float* __restrict__ W2) {
    int i = blockIdx.x * blockDim.x + threadIdx.x;
    if (i >= NLAYERS * 2 * HID * HID) return;
    int e = i & (HID * HID - 1);
    int m = (i >> 14) & 1;           // 0 = W1, 1 = W2
    int l = i >> 15;                 // layer
    int k = e >> 7, n = e & 127;
    const float* W = (m ? W2 : W1) + (size_t)l * HID * HID;
    float v = W[k * HID + n];
    __nv_bfloat16 hi = __float2bfloat16(v);
    __nv_bfloat16 lo = __float2bfloat16(v - __bfloat162float(hi));
    __nv_bfloat16* base = g_wsp + ((size_t)l * 4 + m * 2) * HID * HID;
    base[n * HID + k] = hi;
    base[HID * HID + n * HID + k] = lo;
}
__global__ void wsplit_c_kernel(const float* __restrict__ Wc) {
    int i = blockIdx.x * blockDim.x + threadIdx.x;
    if (i >= OUTC * HID) return;
    int n = i / HID, k = i - n * HID;
    float v = Wc[k * OUTC + n];
    __nv_bfloat16 hi = __float2bfloat16(v);
    __nv_bfloat16 lo = __float2bfloat16(v - __bfloat162float(hi));
    g_wc[n * HID + k] = hi;
    g_wc[64 * HID + n * HID + k] = lo;
}

// ===== gather: z[d,:] = h[d,:] + sum_{s in N(d)} h[s,:] -> split bf16 ======
__global__ __launch_bounds__(256) void gather_kernel(
        const float* __restrict__ h,
        const int* __restrict__ rowptr, const int* __restrict__ col) {
    int node = (blockIdx.x * blockDim.x + threadIdx.x) >> 5;
    if (node >= NNODES) return;
    int lane = threadIdx.x & 31;
    int beg = rowptr[node], end = rowptr[node + 1];
    float4 acc = *(const float4*)(h + (size_t)node * HID + lane * 4);
    int j = beg;
    while (j < end) {
        int n = min(32, end - j);
        int myc = (lane < n) ? col[j + lane] : 0;
        int t = 0;
        for (; t + 7 < n; t += 8) {   // 8-way MLP on the dependent L2 loads
            float4 vv[8];
            #pragma unroll
            for (int u = 0; u < 8; u++) {
                int s = __shfl_sync(~0u, myc, t + u);
                vv[u] = *(const float4*)(h + (size_t)s * HID + lane * 4);
            }
            #pragma unroll
            for (int u = 0; u < 8; u++) {
                acc.x += vv[u].x; acc.y += vv[u].y;
                acc.z += vv[u].z; acc.w += vv[u].w;
            }
        }
        for (; t + 3 < n; t += 4) {
            float4 vv[4];
            #pragma unroll
            for (int u = 0; u < 4; u++) {
                int s = __shfl_sync(~0u, myc, t + u);
                vv[u] = *(const float4*)(h + (size_t)s * HID + lane * 4);
            }
            #pragma unroll
            for (int u = 0; u < 4; u++) {
                acc.x += vv[u].x; acc.y += vv[u].y;
                acc.z += vv[u].z; acc.w += vv[u].w;
            }
        }
        for (; t < n; t++) {
            int s = __shfl_sync(~0u, myc, t);
            float4 v = *(const float4*)(h + (size_t)s * HID + lane * 4);
            acc.x += v.x; acc.y += v.y; acc.z += v.z; acc.w += v.w;
        }
        j += n;
    }
    float f[4] = {acc.x, acc.y, acc.z, acc.w};
    uint32_t hw[2], lw[2];
    #pragma unroll
    for (int p = 0; p < 2; p++) {
        float v0 = f[2 * p], v1 = f[2 * p + 1];
        __nv_bfloat16 h0 = __float2bfloat16(v0), h1 = __float2bfloat16(v1);
        hw[p] = (uint32_t)__bfloat16_as_ushort(h0) |
                ((uint32_t)__bfloat16_as_ushort(h1) << 16);
        lw[p] = pack_bf16x2(v0 - __bfloat162float(h0), v1 - __bfloat162float(h1));
    }
    size_t off = (size_t)node * HID + lane * 4;   // bf16 elements
    *(uint2*)((char*)g_zhi + off * 2) = make_uint2(hw[0], hw[1]);
    *(uint2*)((char*)g_zlo + off * 2) = make_uint2(lw[0], lw[1]);
}

// ===================== tensor-core fused GIN MLP (mma.sync) ================
// SMEM rows padded to 272B (17 x 16B) -> ldmatrix conflict-free.
// Layout: Ahi, Alo, B1hi, B1lo, B2hi, B2lo (6 x 34816B) + biases.
#define SROW 272
#define ATB  (128 * SROW)
#define MLP_SMEM (6 * ATB + 1536)

__device__ __forceinline__ void stage_mat(char* dst, const uint4* src,
                                          int tid, int nrow) {
    for (int i = tid; i < nrow * 16; i += 256) {
        int row = i >> 4, ch = i & 15;
        *(uint4*)(dst + row * SROW + ch * 16) = src[i];
    }
}

// One GEMM phase: acc += Ahi*Bhi + Ahi*Blo + Alo*Bhi (split terms).
template <int NJP>
__device__ __forceinline__ void phase(float (*acc)[4], uint32_t aA, uint32_t aB) {
    #pragma unroll 1
    for (int t = 0; t < 3; t++) {
        uint32_t aa = aA + ((t == 2) ? ATB : 0);
        uint32_t bb = aB + ((t == 1) ? ATB : 0);
        #pragma unroll
        for (int kc = 0; kc < 8; kc++) {
            uint32_t a[4];
            ldsm_x4(a, aa + kc * 32);
            #pragma unroll
            for (int jp = 0; jp < NJP; jp++) {
                uint32_t b[4];
                ldsm_x4(b, bb + jp * 16 * SROW + kc * 32);
                mma16816(acc[2 * jp],     a, b);
                mma16816(acc[2 * jp + 1], a, b + 2);
            }
        }
    }
}

// relu + hi/lo split of acc back into the A tiles (warp-local rows).
__device__ __forceinline__ void epi_to_smem(float (*acc)[4], char* ah, char* al,
                                            int warp, int lane) {
    int rl = lane >> 2;
    int rowL = warp * 16 + rl, rowH = rowL + 8;
    #pragma unroll
    for (int j = 0; j < 16; j++) {
        int boff = 16 * j + (lane & 3) * 4;
        float v0 = fmaxf(acc[j][0], 0.f), v1 = fmaxf(acc[j][1], 0.f);
        float v2 = fmaxf(acc[j][2], 0.f), v3 = fmaxf(acc[j][3], 0.f);
        __nv_bfloat16 h0 = __float2bfloat16(v0), h1 = __float2bfloat16(v1);
        __nv_bfloat16 h2 = __float2bfloat16(v2), h3 = __float2bfloat16(v3);
        *(uint32_t*)(ah + rowL * SROW + boff) =
            (uint32_t)__bfloat16_as_ushort(h0) |
            ((uint32_t)__bfloat16_as_ushort(h1) << 16);
        *(uint32_t*)(ah + rowH * SROW + boff) =
            (uint32_t)__bfloat16_as_ushort(h2) |
            ((uint32_t)__bfloat16_as_ushort(h3) << 16);
        *(uint32_t*)(al + rowL * SROW + boff) =
            pack_bf16x2(v0 - __bfloat162float(h0), v1 - __bfloat162float(h1));
        *(uint32_t*)(al + rowH * SROW + boff) =
            pack_bf16x2(v2 - __bfloat162float(h2), v3 - __bfloat162float(h3));
    }
}

__global__ __launch_bounds__(256) void mlp_mma_kernel(
        float* __restrict__ hout, int layer, int last,
        const float* __restrict__ b1, const float* __restrict__ b2,
        const float* __restrict__ bc, float* __restrict__ out) {
    extern __shared__ char sm[];
    char* ah = sm;
    char* al = sm + ATB;
    char* b1h = sm + 2 * ATB;          // also Wc slot for last layer
    char* b2h = sm + 4 * ATB;
    float* bs1 = (float*)(sm + 6 * ATB);
    float* bs2 = bs1 + HID;
    float* bs3 = bs2 + HID;            // 64 floats (bc padded)

    const int tid = threadIdx.x;
    const int warp = tid >> 5, lane = tid & 31;
    const int tile = blockIdx.x;
    const int row0 = tile * 128;
    const int rmax = NNODES - row0;

    // ---- stage A (split z) + W1^T + W2^T (split) + biases ----
    stage_mat(ah,  (const uint4*)((const char*)g_zhi + (size_t)tile * 32768), tid, 128);
    stage_mat(al,  (const uint4*)((const char*)g_zlo + (size_t)tile * 32768), tid, 128);
    stage_mat(b1h, (const uint4*)(g_wsp + ((size_t)layer * 4 + 0) * HID * HID), tid, 128);
    stage_mat(b1h + ATB, (const uint4*)(g_wsp + ((size_t)layer * 4 + 1) * HID * HID), tid, 128);
    stage_mat(b2h, (const uint4*)(g_wsp + ((size_t)layer * 4 + 2) * HID * HID), tid, 128);
    stage_mat(b2h + ATB, (const uint4*)(g_wsp + ((size_t)layer * 4 + 3) * HID * HID), tid, 128);
    if (tid < HID) { bs1[tid] = b1[tid]; bs2[tid] = b2[tid]; }
    if (tid < 64)  bs3[tid] = (tid < OUTC) ? bc[tid] : 0.f;
    __syncthreads();

    // ldmatrix lane addressing
    const int rr = lane & 7, g = lane >> 3;
    const uint32_t aA = smem_u32(ah) +
        (warp * 16 + (g & 1) * 8 + rr) * SROW + (g >> 1) * 16;
    const uint32_t bOff = ((g >> 1) * 8 + rr) * SROW + (g & 1) * 16;
    const uint32_t aB1 = smem_u32(b1h) + bOff;
    const uint32_t aB2 = smem_u32(b2h) + bOff;

    const int cl = (lane & 3) * 2;
    const int rl = lane >> 2;

    float acc[16][4];

    // ---- phase 1: hidden = relu(z @ W1 + b1) ----
    #pragma unroll
    for (int j = 0; j < 16; j++) {
        float v0 = bs1[8 * j + cl], v1 = bs1[8 * j + cl + 1];
        acc[j][0] = v0; acc[j][1] = v1; acc[j][2] = v0; acc[j][3] = v1;
    }
    phase<8>(acc, aA, aB1);
    epi_to_smem(acc, ah, al, warp, lane);   // warp-local rows only

    if (last) {
        __syncthreads();                     // phase-1 B1 reads done everywhere
        stage_mat(b1h, (const uint4*)g_wc, tid, 64);            // Wc hi
        stage_mat(b1h + ATB, (const uint4*)(g_wc + 64 * HID), tid, 64);  // Wc lo
        __syncthreads();
    } else {
        __syncwarp();                        // A rewrite is warp-local; B2 untouched
    }

    // ---- phase 2: hfin = relu(hidden @ W2 + b2) ----
    #pragma unroll
    for (int j = 0; j < 16; j++) {
        float v0 = bs2[8 * j + cl], v1 = bs2[8 * j + cl + 1];
        acc[j][0] = v0; acc[j][1] = v1; acc[j][2] = v0; acc[j][3] = v1;
    }
    phase<8>(acc, aA, aB2);

    if (!last) {
        // epilogue: relu -> hout fp32
        int rowL = warp * 16 + rl, rowH = rowL + 8;
        bool okL = rowL < rmax, okH = rowH < rmax;
        #pragma unroll
        for (int j = 0; j < 16; j++) {
            int c = 8 * j + cl;
            if (okL) {
                float2 o = make_float2(fmaxf(acc[j][0], 0.f), fmaxf(acc[j][1], 0.f));
                *(float2*)(hout + (size_t)(row0 + rowL) * HID + c) = o;
            }
            if (okH) {
                float2 o = make_float2(fmaxf(acc[j][2], 0.f), fmaxf(acc[j][3], 0.f));
                *(float2*)(hout + (size_t)(row0 + rowH) * HID + c) = o;
            }
        }
        return;
    }

    // ---- last layer: keep hfin in SMEM, fused classifier phase ----
    epi_to_smem(acc, ah, al, warp, lane);
    __syncwarp();

    float acc3[8][4];
    #pragma unroll
    for (int j = 0; j < 8; j++) {
        float v0 = bs3[8 * j + cl], v1 = bs3[8 * j + cl + 1];
        acc3[j][0] = v0; acc3[j][1] = v1; acc3[j][2] = v0; acc3[j][3] = v1;
    }
    phase<4>(acc3, aA, aB1);   // B1 slots now hold Wc (split), n = 64

    {
        int rowL = warp * 16 + rl, rowH = rowL + 8;
        bool okL = rowL < rmax, okH = rowH < rmax;
        #pragma unroll
        for (int j = 0; j < 5; j++) {        // cols 0..39 (pairs up to 38/39)
            int c = 8 * j + cl;
            if (okL) {
                float2 o = make_float2(acc3[j][0], acc3[j][1]);
                *(float2*)(out + (size_t)(row0 + rowL) * OUTC + c) = o;
            }
            if (okH) {
                float2 o = make_float2(acc3[j][2], acc3[j][3]);
                *(float2*)(out + (size_t)(row0 + rowH) * OUTC + c) = o;
            }
        }
    }
}

// ---------------- launch ----------------
extern "C" void kernel_launch(void* const* d_in, const int* in_sizes, int n_in,
                              void* d_out, int out_size) {
    (void)in_sizes; (void)n_in; (void)out_size;
    const float* x  = (const float*)d_in[0];
    const int*   ei = (const int*)d_in[2];       // int32 (JAX demotes int64)
    const float* W1 = (const float*)d_in[3];
    const float* b1 = (const float*)d_in[4];
    const float* W2 = (const float*)d_in[5];
    const float* b2 = (const float*)d_in[6];
    const float* Wc = (const float*)d_in[7];
    const float* bc = (const float*)d_in[8];
    float* out = (float*)d_out;

    float* hbuf;
    int *deg, *rowptr, *cur, *col, *bsum;
    cudaGetSymbolAddress((void**)&hbuf, g_h);
    cudaGetSymbolAddress((void**)&deg, g_deg);
    cudaGetSymbolAddress((void**)&rowptr, g_rowptr);
    cudaGetSymbolAddress((void**)&cur, g_cur);
    cudaGetSymbolAddress((void**)&col, g_col);
    cudaGetSymbolAddress((void**)&bsum, g_bsum);

    cudaFuncSetAttribute(mlp_mma_kernel,
                         cudaFuncAttributeMaxDynamicSharedMemorySize, MLP_SMEM);

    const int EB = (NEDGES + 255) / 256;
    const int GB = (NNODES * 32 + 255) / 256;
    const int WB = (NLAYERS * 2 * HID * HID + 255) / 256;

    // weight split/transpose
    wsplit_kernel<<<WB, 256>>>(W1, W2);
    wsplit_c_kernel<<<(OUTC * HID + 255) / 256, 256>>>(Wc);

    // CSR build (parallel 3-pass scan)
    cudaMemsetAsync(deg, 0, NNODES * sizeof(int));
    count_kernel<<<EB, 256>>>(ei, deg);
    bsum_kernel<<<SCB, 256>>>(deg, bsum);
    bscan_kernel<<<1, 64>>>(bsum);
    scan2_kernel<<<SCB, 256>>>(deg, bsum, rowptr, cur);
    fill_kernel<<<EB, 256>>>(ei, cur, col);

    // layer 0 (h = x)
    gather_kernel<<<GB, 256>>>(x, rowptr, col);
    mlp_mma_kernel<<<NTILES, 256, MLP_SMEM>>>(hbuf, 0, 0, b1, b2, bc, out);

    for (int l = 1; l < NLAYERS; l++) {
        gather_kernel<<<GB, 256>>>(hbuf, rowptr, col);
        mlp_mma_kernel<<<NTILES, 256, MLP_SMEM>>>(
            hbuf, l, (l == NLAYERS - 1) ? 1 : 0,
            b1 + (size_t)l * HID, b2 + (size_t)l * HID, bc, out);
    }
}